// round 5
// baseline (speedup 1.0000x reference)
#include <cuda_runtime.h>
#include <cuda_bf16.h>
#include <cstdint>

// Inputs (metadata order):
// 0: hidden_states [B, ITEM] f32
// 1: actions       [B]       i32   (UNUSED by reference)
// 2: rewards       [B]       f32
// 3: discount      []        f32 (scalar)
// 4: targetQs_s    [B, ITEM] f32
// 5: is_done       [B]       bool (uint8)
// 6: W             [1, ITEM] f32
// 7: b             [1]       f32
// out: scalar f32

// Cross-launch scratch for single-kernel grid reduction. Statically zero at
// module load; every launch restores the zero invariant in its last block,
// so graph replays see a clean state. No device allocation (rule-compliant).
__device__ float        g_partial = 0.0f;
__device__ unsigned int g_count   = 0u;

__global__ __launch_bounds__(256, 4)
void dqn_loss_kernel(const float4* __restrict__ hs,
                     const float4* __restrict__ tq,
                     const float4* __restrict__ W4,
                     const float*  __restrict__ rewards,
                     const float*  __restrict__ discount,
                     const unsigned char* __restrict__ is_done,
                     const float*  __restrict__ bias,
                     float* __restrict__ out,
                     int nvec,        // ITEM / 4
                     int item,        // ITEM
                     float invB)
{
    const int row = blockIdx.x;
    const int tid = threadIdx.x;
    const int stride = blockDim.x;          // 256
    const size_t base = (size_t)row * (size_t)nvec;
    const float4* __restrict__ h = hs + base;
    const float4* __restrict__ t = tq + base;

    float q = 0.0f, nq = 0.0f;

    // Manually batched 4x-strided main loop. With 64 regs/thread available
    // (occ 4), ptxas can hoist all 12 LDG.128 of a chunk ahead of the FMAs:
    // MLP_eff ~12 per thread, 8 of them HBM streams.
    int i = tid;
    for (; i + 3 * stride < nvec; i += 4 * stride) {
        float4 w0 = __ldg(&W4[i]);
        float4 w1 = __ldg(&W4[i +     stride]);
        float4 w2 = __ldg(&W4[i + 2 * stride]);
        float4 w3 = __ldg(&W4[i + 3 * stride]);
        float4 a0 = __ldcs(&h[i]);
        float4 a1 = __ldcs(&h[i +     stride]);
        float4 a2 = __ldcs(&h[i + 2 * stride]);
        float4 a3 = __ldcs(&h[i + 3 * stride]);
        float4 c0 = __ldcs(&t[i]);
        float4 c1 = __ldcs(&t[i +     stride]);
        float4 c2 = __ldcs(&t[i + 2 * stride]);
        float4 c3 = __ldcs(&t[i + 3 * stride]);

        q  = fmaf(a0.x, w0.x, q);  q  = fmaf(a0.y, w0.y, q);
        q  = fmaf(a0.z, w0.z, q);  q  = fmaf(a0.w, w0.w, q);
        nq = fmaf(c0.x, w0.x, nq); nq = fmaf(c0.y, w0.y, nq);
        nq = fmaf(c0.z, w0.z, nq); nq = fmaf(c0.w, w0.w, nq);

        q  = fmaf(a1.x, w1.x, q);  q  = fmaf(a1.y, w1.y, q);
        q  = fmaf(a1.z, w1.z, q);  q  = fmaf(a1.w, w1.w, q);
        nq = fmaf(c1.x, w1.x, nq); nq = fmaf(c1.y, w1.y, nq);
        nq = fmaf(c1.z, w1.z, nq); nq = fmaf(c1.w, w1.w, nq);

        q  = fmaf(a2.x, w2.x, q);  q  = fmaf(a2.y, w2.y, q);
        q  = fmaf(a2.z, w2.z, q);  q  = fmaf(a2.w, w2.w, q);
        nq = fmaf(c2.x, w2.x, nq); nq = fmaf(c2.y, w2.y, nq);
        nq = fmaf(c2.z, w2.z, nq); nq = fmaf(c2.w, w2.w, nq);

        q  = fmaf(a3.x, w3.x, q);  q  = fmaf(a3.y, w3.y, q);
        q  = fmaf(a3.z, w3.z, q);  q  = fmaf(a3.w, w3.w, q);
        nq = fmaf(c3.x, w3.x, nq); nq = fmaf(c3.y, w3.y, nq);
        nq = fmaf(c3.z, w3.z, nq); nq = fmaf(c3.w, w3.w, nq);
    }
    // Remainder strides
    for (; i < nvec; i += stride) {
        float4 w = __ldg(&W4[i]);
        float4 a = __ldcs(&h[i]);
        float4 c = __ldcs(&t[i]);
        q  = fmaf(a.x, w.x, q);  q  = fmaf(a.y, w.y, q);
        q  = fmaf(a.z, w.z, q);  q  = fmaf(a.w, w.w, q);
        nq = fmaf(c.x, w.x, nq); nq = fmaf(c.y, w.y, nq);
        nq = fmaf(c.z, w.z, nq); nq = fmaf(c.w, w.w, nq);
    }

    // Scalar tail (ITEM % 4 != 0). Empty for ITEM=10000.
    {
        int tail_start = nvec * 4;
        const float* hsc = (const float*)hs + (size_t)row * item;
        const float* tsc = (const float*)tq + (size_t)row * item;
        const float* wsc = (const float*)W4;
        for (int k = tail_start + tid; k < item; k += stride) {
            float w = __ldg(&wsc[k]);
            q  = fmaf(__ldg(&hsc[k]), w, q);
            nq = fmaf(__ldg(&tsc[k]), w, nq);
        }
    }

    // Warp reduction
    #pragma unroll
    for (int off = 16; off > 0; off >>= 1) {
        q  += __shfl_down_sync(0xFFFFFFFFu, q,  off);
        nq += __shfl_down_sync(0xFFFFFFFFu, nq, off);
    }

    __shared__ float sq[8], snq[8];
    const int wid = tid >> 5;
    const int lid = tid & 31;
    if (lid == 0) { sq[wid] = q; snq[wid] = nq; }
    __syncthreads();

    if (wid == 0) {
        const int nwarps = blockDim.x >> 5;
        float vq  = (lid < nwarps) ? sq[lid]  : 0.0f;
        float vnq = (lid < nwarps) ? snq[lid] : 0.0f;
        #pragma unroll
        for (int off = 4; off > 0; off >>= 1) {
            vq  += __shfl_down_sync(0xFFFFFFFFu, vq,  off);
            vnq += __shfl_down_sync(0xFFFFFFFFu, vnq, off);
        }
        if (lid == 0) {
            float b0 = __ldg(bias);
            float g  = __ldg(discount);
            float Q  = fmaxf(vq  + b0, 0.0f);
            float NQ = fmaxf(vnq + b0, 0.0f);
            float per = fabsf(__ldg(&rewards[row]) + g * NQ - Q);
            if (is_done[row]) per = 0.0f;

            // Single-kernel grid reduction: accumulate, then the last CTA to
            // arrive writes the final value and resets scratch for the next
            // graph replay.
            atomicAdd(&g_partial, per);
            __threadfence();
            unsigned int arrived = atomicAdd(&g_count, 1u);
            if (arrived == gridDim.x - 1u) {
                float total = atomicAdd(&g_partial, 0.0f);  // fenced read
                out[0] = total * invB;
                g_partial = 0.0f;
                g_count   = 0u;
            }
        }
    }
}

extern "C" void kernel_launch(void* const* d_in, const int* in_sizes, int n_in,
                              void* d_out, int out_size)
{
    const float* hidden   = (const float*)d_in[0];
    // d_in[1] = actions (unused by reference)
    const float* rewards  = (const float*)d_in[2];
    const float* discount = (const float*)d_in[3];
    const float* targetQ  = (const float*)d_in[4];
    const unsigned char* is_done = (const unsigned char*)d_in[5];
    const float* W        = (const float*)d_in[6];
    const float* bias     = (const float*)d_in[7];
    float* out            = (float*)d_out;

    const int B    = in_sizes[2];            // rewards element count (8192)
    const int ITEM = in_sizes[0] / B;        // 10000
    const int nvec = ITEM / 4;               // 2500
    const float invB = 1.0f / (float)B;

    dqn_loss_kernel<<<B, 256>>>((const float4*)hidden,
                                (const float4*)targetQ,
                                (const float4*)W,
                                rewards, discount, is_done, bias,
                                out, nvec, ITEM, invB);
}

// round 6
// speedup vs baseline: 1.0405x; 1.0405x over previous
#include <cuda_runtime.h>
#include <cuda_bf16.h>
#include <cstdint>

// Inputs (metadata order):
// 0: hidden_states [B, ITEM] f32
// 1: actions       [B]       i32   (UNUSED by reference)
// 2: rewards       [B]       f32
// 3: discount      []        f32 (scalar)
// 4: targetQs_s    [B, ITEM] f32
// 5: is_done       [B]       bool (uint8)
// 6: W             [1, ITEM] f32
// 7: b             [1]       f32
// out: scalar f32

// Cross-launch scratch for single-kernel grid reduction. Statically zero at
// module load; the last CTA of every launch restores the zero invariant, so
// graph replays see clean state. No device allocation (rule-compliant).
__device__ float        g_partial = 0.0f;
__device__ unsigned int g_count   = 0u;

__global__ __launch_bounds__(256, 8)
void dqn_loss_kernel(const float4* __restrict__ hs,
                     const float4* __restrict__ tq,
                     const float4* __restrict__ W4,
                     const float*  __restrict__ rewards,
                     const float*  __restrict__ discount,
                     const unsigned char* __restrict__ is_done,
                     const float*  __restrict__ bias,
                     float* __restrict__ out,
                     int nvec,        // ITEM / 4
                     int item,        // ITEM
                     float invB)
{
    const int row = blockIdx.x;
    const int tid = threadIdx.x;
    const size_t base = (size_t)row * (size_t)nvec;
    const float4* __restrict__ h = hs + base;
    const float4* __restrict__ t = tq + base;

    float q = 0.0f, nq = 0.0f;

    // Main vectorized streaming loop (proven R4 config: occ 8, 32 regs,
    // DRAM 85%). Streams use evict-first (__ldcs): read-once data should not
    // displace the L2-resident W vector.
    #pragma unroll 4
    for (int i = tid; i < nvec; i += blockDim.x) {
        float4 w = __ldg(&W4[i]);
        float4 a = __ldcs(&h[i]);
        float4 c = __ldcs(&t[i]);
        q  = fmaf(a.x, w.x, q);  q  = fmaf(a.y, w.y, q);
        q  = fmaf(a.z, w.z, q);  q  = fmaf(a.w, w.w, q);
        nq = fmaf(c.x, w.x, nq); nq = fmaf(c.y, w.y, nq);
        nq = fmaf(c.z, w.z, nq); nq = fmaf(c.w, w.w, nq);
    }

    // Scalar tail (ITEM % 4 != 0). Empty for ITEM=10000.
    {
        int tail_start = nvec * 4;
        const float* hsc = (const float*)hs + (size_t)row * item;
        const float* tsc = (const float*)tq + (size_t)row * item;
        const float* wsc = (const float*)W4;
        for (int k = tail_start + tid; k < item; k += blockDim.x) {
            float w = __ldg(&wsc[k]);
            q  = fmaf(__ldg(&hsc[k]), w, q);
            nq = fmaf(__ldg(&tsc[k]), w, nq);
        }
    }

    // Warp reduction
    #pragma unroll
    for (int off = 16; off > 0; off >>= 1) {
        q  += __shfl_down_sync(0xFFFFFFFFu, q,  off);
        nq += __shfl_down_sync(0xFFFFFFFFu, nq, off);
    }

    __shared__ float sq[8], snq[8];
    const int wid = tid >> 5;
    const int lid = tid & 31;
    if (lid == 0) { sq[wid] = q; snq[wid] = nq; }
    __syncthreads();

    if (wid == 0) {
        const int nwarps = blockDim.x >> 5;
        float vq  = (lid < nwarps) ? sq[lid]  : 0.0f;
        float vnq = (lid < nwarps) ? snq[lid] : 0.0f;
        #pragma unroll
        for (int off = 4; off > 0; off >>= 1) {
            vq  += __shfl_down_sync(0xFFFFFFFFu, vq,  off);
            vnq += __shfl_down_sync(0xFFFFFFFFu, vnq, off);
        }
        if (lid == 0) {
            float b0 = __ldg(bias);
            float g  = __ldg(discount);
            float Q  = fmaxf(vq  + b0, 0.0f);
            float NQ = fmaxf(vnq + b0, 0.0f);
            float per = fabsf(__ldg(&rewards[row]) + g * NQ - Q);
            if (is_done[row]) per = 0.0f;

            // Single-kernel grid reduction: accumulate; the last CTA to
            // arrive publishes the result and resets scratch for replay.
            atomicAdd(&g_partial, per);
            __threadfence();
            unsigned int arrived = atomicAdd(&g_count, 1u);
            if (arrived == gridDim.x - 1u) {
                float total = atomicAdd(&g_partial, 0.0f);  // fenced read
                out[0] = total * invB;
                g_partial = 0.0f;
                g_count   = 0u;
            }
        }
    }
}

extern "C" void kernel_launch(void* const* d_in, const int* in_sizes, int n_in,
                              void* d_out, int out_size)
{
    const float* hidden   = (const float*)d_in[0];
    // d_in[1] = actions (unused by reference)
    const float* rewards  = (const float*)d_in[2];
    const float* discount = (const float*)d_in[3];
    const float* targetQ  = (const float*)d_in[4];
    const unsigned char* is_done = (const unsigned char*)d_in[5];
    const float* W        = (const float*)d_in[6];
    const float* bias     = (const float*)d_in[7];
    float* out            = (float*)d_out;

    const int B    = in_sizes[2];            // rewards element count (8192)
    const int ITEM = in_sizes[0] / B;        // 10000
    const int nvec = ITEM / 4;               // 2500
    const float invB = 1.0f / (float)B;

    dqn_loss_kernel<<<B, 256>>>((const float4*)hidden,
                                (const float4*)targetQ,
                                (const float4*)W,
                                rewards, discount, is_done, bias,
                                out, nvec, ITEM, invB);
}